// round 16
// baseline (speedup 1.0000x reference)
#include <cuda_runtime.h>
#include <cuda_bf16.h>
#include <math.h>
#include <cstdint>

#define B_    64
#define LS    256
#define LW    256
#define MM    16
#define NSTEP 10
#define HH    1024
#define DD    1280
#define BM    (B_*MM)                      /* 1024 */
#define S_ENTRIES (B_*(NSTEP+1)*LS)        /* 180224: real-part floats */
#define RHO_OFF   S_ENTRIES

// -------- scratch ----------------------------------------------------------
__device__ float g_xs[BM*512];
__device__ float g_S[11u*BM*HH];
__device__ float g_yp[11*MM*HH];
__device__ float g_dyn[2*B_*HH];
__device__ float g_rho[BM];
__device__ float g_g[B_*HH];
__device__ float g_eta[B_*LS];
__device__ float g_phi[B_*LS];
__device__ float g_srsi[B_*2*LS];
// bf16 split operands for tensor k_static
__device__ __nv_bfloat16 g_xsh[BM*512];
__device__ __nv_bfloat16 g_xsl[BM*512];
__device__ __nv_bfloat16 g_WTh[11u*1024*512];   // [z][n][k] = W[z][512+k][n]
__device__ __nv_bfloat16 g_WTl[11u*1024*512];

// cp.async / ldmatrix helpers
#define CP_ASYNC16(dst, src) \
    asm volatile("cp.async.cg.shared.global [%0], [%1], 16;" \
                 :: "r"(dst), "l"(src) : "memory")
#define CP_COMMIT() asm volatile("cp.async.commit_group;" ::: "memory")
#define CP_WAIT(n)  asm volatile("cp.async.wait_group %0;" :: "n"(n) : "memory")
#define LDM_X4(r0,r1,r2,r3,a) \
    asm volatile("ldmatrix.sync.aligned.m8n8.x4.shared.b16 {%0,%1,%2,%3}, [%4];" \
                 : "=r"(r0), "=r"(r1), "=r"(r2), "=r"(r3) : "r"(a))

// ---------------------------------------------------------------------------
// P0: build xs (+bf16 hi/lo); phi copy + sincos + out slot 0; zero scratch
__global__ void k_prep(const float* __restrict__ phi,
                       const float* __restrict__ wr,
                       const float* __restrict__ wi,
                       float* __restrict__ out)
{
    int idx = blockIdx.x*256 + threadIdx.x;
    if (idx < BM*512) {
        int bm = idx >> 9, k = idx & 511;
        int b = bm >> 4, m = bm & 15;
        float v;
        if (k < 256) v = wr[((size_t)b*LW + k)*MM + m];
        else         v = wi[((size_t)b*LW + (k-256))*MM + m];
        g_xs[idx] = v;
        __nv_bfloat16 h = __float2bfloat16(v);
        g_xsh[idx] = h;
        g_xsl[idx] = __float2bfloat16(v - __bfloat162float(h));
    }
    if (idx < 2*B_*HH) g_dyn[idx] = 0.f;
    if (idx < 11*MM*HH) g_yp[idx] = 0.f;
    if (idx < B_*LS) {
        float p = phi[idx];
        g_phi[idx] = p;
        float sn, cs;
        sincosf(p, &sn, &cs);
        int b = idx >> 8, l = idx & 255;
        g_srsi[b*2*LS + l]      = cs;
        g_srsi[b*2*LS + LS + l] = sn;
        out[((size_t)b*(NSTEP+1) + 0)*LS + l] = cs;
    }
}

// W transpose+convert: WT[z][n][k] = W[z][512+k][n]  (bf16 hi/lo)
__global__ void k_wconv(const float* __restrict__ W1, const float* __restrict__ V1)
{
    __shared__ float t[32][33];
    int z = blockIdx.z, k0 = blockIdx.x*32, n0 = blockIdx.y*32;
    const float* src = (z < 10) ? (W1 + (size_t)z*DD*HH + (size_t)512*HH)
                                : (V1 + (size_t)512*HH);
    int tx = threadIdx.x & 31, ty = threadIdx.x >> 5;
    #pragma unroll
    for (int i = 0; i < 4; i++) {
        int ky = ty + i*8;
        t[ky][tx] = src[(size_t)(k0+ky)*HH + n0 + tx];
    }
    __syncthreads();
    #pragma unroll
    for (int i = 0; i < 4; i++) {
        int ny = ty + i*8;
        float v = t[tx][ny];
        __nv_bfloat16 h = __float2bfloat16(v);
        size_t o = ((size_t)z*1024 + n0 + ny)*512 + k0 + tx;
        g_WTh[o] = h;
        g_WTl[o] = __float2bfloat16(v - __bfloat162float(h));
    }
}

// P2 (split-l): yp[z][m][h] += partial; grid (4, 8, 11).
__global__ __launch_bounds__(256) void k_yp(
    const float* __restrict__ y,  const float* __restrict__ W1,
    const float* __restrict__ V1, const float* __restrict__ b1,
    const float* __restrict__ c1)
{
    int h  = blockIdx.x*256 + threadIdx.x;
    int ls = blockIdx.y;
    int z  = blockIdx.z;
    const float* Wy = (z < 10) ? (W1 + (size_t)z*DD*HH + (size_t)1024*HH)
                               : (V1 + (size_t)1024*HH);

    __shared__ float ys[32][16];
    for (int t = threadIdx.x; t < 32*16; t += 256)
        ys[t >> 4][t & 15] = y[(ls*32 + (t >> 4))*MM + (t & 15)];
    __syncthreads();

    float acc[16];
    #pragma unroll
    for (int m = 0; m < 16; m++) acc[m] = 0.f;
    #pragma unroll 4
    for (int l = 0; l < 32; l++) {
        float wv = Wy[(size_t)(ls*32 + l)*HH + h];
        #pragma unroll
        for (int m = 0; m < 16; m++) acc[m] += ys[l][m] * wv;
    }
    if (ls == 0) {
        float bias = (z < 10) ? b1[z*HH + h] : c1[h];
        #pragma unroll
        for (int m = 0; m < 16; m++) acc[m] += bias;
    }
    #pragma unroll
    for (int m = 0; m < 16; m++)
        atomicAdd(&g_yp[((size_t)z*MM + m)*HH + h], acc[m]);
}

// P1: 128x128 tile, K16 chunks, 3-stage cp.async, ldmatrix fragments.
#define SPAD 24                            /* halfword stride, 48B rows */
#define CHW  (128*SPAD)                    /* hw per operand stage (3072) */
#define SMEM_TC_BYTES (12*CHW*2)           /* 4 ops x 3 stages = 73728B */
__global__ __launch_bounds__(256) void k_static_mma()
{
    extern __shared__ __nv_bfloat16 smtc[];

    int tid = threadIdx.x;
    int wid = tid >> 5, lane = tid & 31;
    int wr = wid >> 2, wc = wid & 3;
    int col0 = blockIdx.x*128, row0 = blockIdx.y*128, z = blockIdx.z;

    const __nv_bfloat16* Gm[4];
    Gm[0] = g_xsh + (size_t)row0*512;
    Gm[1] = g_xsl + (size_t)row0*512;
    Gm[2] = g_WTh + ((size_t)z*1024 + col0)*512;
    Gm[3] = g_WTl + ((size_t)z*1024 + col0)*512;

    float acc[4][4][4];
    #pragma unroll
    for (int mt = 0; mt < 4; mt++)
        #pragma unroll
        for (int nt = 0; nt < 4; nt++)
            #pragma unroll
            for (int r = 0; r < 4; r++) acc[mt][nt][r] = 0.f;

    uint32_t smbase = (uint32_t)__cvta_generic_to_shared(smtc);
    // staging: 128 rows x 16 hw per op per chunk; thread: row=tid>>1, 8hw half
    int sr = tid >> 1, sg = tid & 1;
    uint32_t sdst = (uint32_t)(sr*SPAD + sg*8)*2;
    size_t   ssrc = (size_t)sr*512 + sg*8;

    // ldmatrix addresses
    int a_row = wr*64 + (lane & 15);
    int a_k   = (lane >> 4) * 8;
    int b_row = wc*32 + ((lane >> 4) << 3) + (lane & 7);
    int b_k   = ((lane >> 3) & 1) * 8;

    // prologue: stage chunks 0, 1
    #pragma unroll
    for (int s = 0; s < 2; s++) {
        #pragma unroll
        for (int op = 0; op < 4; op++)
            CP_ASYNC16(smbase + (uint32_t)((op*3 + s)*CHW)*2 + sdst,
                       Gm[op] + ssrc + (size_t)s*16);
        CP_COMMIT();
    }
    CP_WAIT(1);
    __syncthreads();

    for (int kc = 0; kc < 32; kc++) {
        if (kc + 2 < 32) {
            int s = (kc + 2) % 3;
            #pragma unroll
            for (int op = 0; op < 4; op++)
                CP_ASYNC16(smbase + (uint32_t)((op*3 + s)*CHW)*2 + sdst,
                           Gm[op] + ssrc + (size_t)(kc+2)*16);
            CP_COMMIT();
        }

        int cur = kc % 3;
        uint32_t sAh = smbase + (uint32_t)((0*3+cur)*CHW)*2;
        uint32_t sAl = smbase + (uint32_t)((1*3+cur)*CHW)*2;
        uint32_t sBh = smbase + (uint32_t)((2*3+cur)*CHW)*2;
        uint32_t sBl = smbase + (uint32_t)((3*3+cur)*CHW)*2;

        uint32_t bh[4][2], bl[4][2];
        #pragma unroll
        for (int p = 0; p < 2; p++) {
            uint32_t off = (uint32_t)((b_row + p*16)*SPAD + b_k)*2;
            LDM_X4(bh[2*p][0], bh[2*p][1], bh[2*p+1][0], bh[2*p+1][1],
                   sBh + off);
            LDM_X4(bl[2*p][0], bl[2*p][1], bl[2*p+1][0], bl[2*p+1][1],
                   sBl + off);
        }
        #pragma unroll
        for (int mt = 0; mt < 4; mt++) {
            uint32_t off = (uint32_t)((a_row + mt*16)*SPAD + a_k)*2;
            uint32_t ah[4], al[4];
            LDM_X4(ah[0], ah[1], ah[2], ah[3], sAh + off);
            LDM_X4(al[0], al[1], al[2], al[3], sAl + off);
            #pragma unroll
            for (int nt = 0; nt < 4; nt++) {
                float* c = acc[mt][nt];
                asm volatile(
                  "mma.sync.aligned.m16n8k16.row.col.f32.bf16.bf16.f32 "
                  "{%0,%1,%2,%3}, {%4,%5,%6,%7}, {%8,%9}, {%0,%1,%2,%3};"
                  : "+f"(c[0]), "+f"(c[1]), "+f"(c[2]), "+f"(c[3])
                  : "r"(ah[0]), "r"(ah[1]), "r"(ah[2]), "r"(ah[3]),
                    "r"(bh[nt][0]), "r"(bh[nt][1]));
                asm volatile(
                  "mma.sync.aligned.m16n8k16.row.col.f32.bf16.bf16.f32 "
                  "{%0,%1,%2,%3}, {%4,%5,%6,%7}, {%8,%9}, {%0,%1,%2,%3};"
                  : "+f"(c[0]), "+f"(c[1]), "+f"(c[2]), "+f"(c[3])
                  : "r"(ah[0]), "r"(ah[1]), "r"(ah[2]), "r"(ah[3]),
                    "r"(bl[nt][0]), "r"(bl[nt][1]));
                asm volatile(
                  "mma.sync.aligned.m16n8k16.row.col.f32.bf16.bf16.f32 "
                  "{%0,%1,%2,%3}, {%4,%5,%6,%7}, {%8,%9}, {%0,%1,%2,%3};"
                  : "+f"(c[0]), "+f"(c[1]), "+f"(c[2]), "+f"(c[3])
                  : "r"(al[0]), "r"(al[1]), "r"(al[2]), "r"(al[3]),
                    "r"(bh[nt][0]), "r"(bh[nt][1]));
            }
        }

        if (kc + 2 < 32) { CP_WAIT(1); } else { CP_WAIT(0); }
        __syncthreads();
    }

    float* C = g_S + (size_t)z*BM*HH;
    #pragma unroll
    for (int mt = 0; mt < 4; mt++) {
        int mrow = row0 + wr*64 + mt*16 + (lane >> 2);
        #pragma unroll
        for (int nt = 0; nt < 4; nt++) {
            int col = col0 + wc*32 + nt*8 + (lane & 3)*2;
            float* c = acc[mt][nt];
            *(float2*)(&C[(size_t)mrow*HH + col])     = make_float2(c[0], c[1]);
            *(float2*)(&C[(size_t)(mrow+8)*HH + col]) = make_float2(c[2], c[3]);
        }
    }
}

// K2: split-K dyn GEMM. grid (16 col-tiles, 16 K-slices of 32, 2 z) = 512.
__global__ __launch_bounds__(256) void k_dyn(const float* __restrict__ W1,
                                             const float* __restrict__ V1, int n)
{
    if (blockIdx.z == 0 && blockIdx.y == 0) {
        int t = blockIdx.x*256 + threadIdx.x;
        #pragma unroll
        for (int i = 0; i < 16; i++) g_g[t + i*4096] = 0.f;
        #pragma unroll
        for (int i = 0; i < 4; i++) g_eta[t + i*4096] = 0.f;
    }

    int z = blockIdx.z;
    const float* Bmat = (z == 0) ? (W1 + (size_t)n*DD*HH) : V1;
    float* C = g_dyn + (size_t)z*B_*HH;
    const float* A = g_srsi;
    int col0 = blockIdx.x*64;
    int kbeg = blockIdx.y*32, kend = kbeg + 32;

    __shared__ float As[8][64];
    __shared__ float Bs[8][64];
    int tid = threadIdx.x;
    int tx = tid & 15, ty = tid >> 4;
    float acc[4][4];
    #pragma unroll
    for (int i = 0; i < 4; i++)
        #pragma unroll
        for (int j = 0; j < 4; j++) acc[i][j] = 0.f;

    int arow = tid >> 2, acol = (tid & 3) << 1;
    int brow = tid >> 5, bcol = (tid & 31) << 1;

    for (int k0 = kbeg; k0 < kend; k0 += 8) {
        float2 av = *(const float2*)(A + (size_t)arow*512 + k0 + acol);
        As[acol][arow] = av.x; As[acol+1][arow] = av.y;
        float2 bv = *(const float2*)(Bmat + (size_t)(k0+brow)*HH + col0 + bcol);
        Bs[brow][bcol] = bv.x; Bs[brow][bcol+1] = bv.y;
        __syncthreads();
        #pragma unroll
        for (int k = 0; k < 8; k++) {
            float a[4], bb[4];
            #pragma unroll
            for (int i = 0; i < 4; i++) a[i]  = As[k][ty*4+i];
            #pragma unroll
            for (int j = 0; j < 4; j++) bb[j] = Bs[k][tx*4+j];
            #pragma unroll
            for (int i = 0; i < 4; i++)
                #pragma unroll
                for (int j = 0; j < 4; j++) acc[i][j] += a[i]*bb[j];
        }
        __syncthreads();
    }
    #pragma unroll
    for (int i = 0; i < 4; i++)
        #pragma unroll
        for (int j = 0; j < 4; j++)
            atomicAdd(&C[(size_t)(ty*4+i)*HH + col0 + tx*4 + j], acc[i][j]);
}

// K3: h/rho with float4 streams; accumulates rho*h into g_g; writes rho.
__global__ void k_hrho(const float* __restrict__ V2, const float* __restrict__ c2,
                       float* __restrict__ out, int n)
{
    int bm = blockIdx.x, b = bm >> 4, m = bm & 15;
    const float4* S1 = (const float4*)(g_S + (size_t)n*BM*HH  + (size_t)bm*HH);
    const float4* SV = (const float4*)(g_S + (size_t)10*BM*HH + (size_t)bm*HH);
    const float4* y1 = (const float4*)(g_yp + ((size_t)n*MM  + m)*HH);
    const float4* yV = (const float4*)(g_yp + ((size_t)10*MM + m)*HH);
    const float4* d1 = (const float4*)(g_dyn + (size_t)b*HH);
    const float4* dV = (const float4*)(g_dyn + (size_t)B_*HH + (size_t)b*HH);
    const float4* V4 = (const float4*)V2;

    int j = threadIdx.x;                     // 256 threads x float4 = 1024
    float4 a1 = d1[j], s1 = S1[j], b1v = y1[j];
    float4 aV = dV[j], sV = SV[j], bVv = yV[j];
    float4 vv = V4[j];
    float4 h;
    h.x = fmaxf(a1.x + s1.x + b1v.x, 0.f);
    h.y = fmaxf(a1.y + s1.y + b1v.y, 0.f);
    h.z = fmaxf(a1.z + s1.z + b1v.z, 0.f);
    h.w = fmaxf(a1.w + s1.w + b1v.w, 0.f);
    float acc = fmaxf(aV.x + sV.x + bVv.x, 0.f) * vv.x
              + fmaxf(aV.y + sV.y + bVv.y, 0.f) * vv.y
              + fmaxf(aV.z + sV.z + bVv.z, 0.f) * vv.z
              + fmaxf(aV.w + sV.w + bVv.w, 0.f) * vv.w;

    #pragma unroll
    for (int off = 16; off; off >>= 1)
        acc += __shfl_down_sync(0xffffffffu, acc, off);
    __shared__ float red[8];
    __shared__ float s_r;
    if ((threadIdx.x & 31) == 0) red[threadIdx.x >> 5] = acc;
    __syncthreads();
    if (threadIdx.x == 0) {
        float t = 0.f;
        #pragma unroll
        for (int i = 0; i < 8; i++) t += red[i];
        float r = 1.f/(1.f + expf(-(t + c2[0])));
        s_r = r;
        g_rho[bm] = r;
        out[RHO_OFF + ((size_t)b*NSTEP + n)*MM + m] = r;
    }
    __syncthreads();
    float r = s_r;
    float* gg = g_g + (size_t)b*HH + 4*j;
    atomicAdd(gg+0, r*h.x);
    atomicAdd(gg+1, r*h.y);
    atomicAdd(gg+2, r*h.z);
    atomicAdd(gg+3, r*h.w);
}

// K4: split-K eta GEMM, atomicAdd into g_eta.
__global__ __launch_bounds__(256) void k_etap(const float* __restrict__ W2, int n)
{
    const float* A = g_g;
    const float* Bmat = W2 + (size_t)n*HH*LS;
    int col0 = blockIdx.x*64;
    int kbeg = blockIdx.y*64, kend = kbeg + 64;

    __shared__ float As[8][64];
    __shared__ float Bs[8][64];
    int tid = threadIdx.x;
    int tx = tid & 15, ty = tid >> 4;
    float acc[4][4];
    #pragma unroll
    for (int i = 0; i < 4; i++)
        #pragma unroll
        for (int j = 0; j < 4; j++) acc[i][j] = 0.f;

    int arow = tid >> 2, acol = (tid & 3) << 1;
    int brow = tid >> 5, bcol = (tid & 31) << 1;

    for (int k0 = kbeg; k0 < kend; k0 += 8) {
        float2 av = *(const float2*)(A + (size_t)arow*HH + k0 + acol);
        As[acol][arow] = av.x; As[acol+1][arow] = av.y;
        float2 bv = *(const float2*)(Bmat + (size_t)(k0+brow)*LS + col0 + bcol);
        Bs[brow][bcol] = bv.x; Bs[brow][bcol+1] = bv.y;
        __syncthreads();
        #pragma unroll
        for (int k = 0; k < 8; k++) {
            float a[4], bb[4];
            #pragma unroll
            for (int i = 0; i < 4; i++) a[i]  = As[k][ty*4+i];
            #pragma unroll
            for (int j = 0; j < 4; j++) bb[j] = Bs[k][tx*4+j];
            #pragma unroll
            for (int i = 0; i < 4; i++)
                #pragma unroll
                for (int j = 0; j < 4; j++) acc[i][j] += a[i]*bb[j];
        }
        __syncthreads();
    }
    #pragma unroll
    for (int i = 0; i < 4; i++)
        #pragma unroll
        for (int j = 0; j < 4; j++)
            atomicAdd(&g_eta[(size_t)(ty*4+i)*LS + col0 + tx*4 + j], acc[i][j]);
}

// K5: phi update + cis + out; zero g_dyn for next step.
__global__ void k_update(const float* __restrict__ b2, float* __restrict__ out,
                         int n)
{
    int idx = blockIdx.x*256 + threadIdx.x;
    int b = idx >> 8, l = idx & 255;
    float e = g_eta[idx];
    float rs = 0.f;
    #pragma unroll
    for (int m = 0; m < 16; m++) rs += g_rho[b*16+m];
    e += rs * b2[(size_t)n*LS + l];
    float p = g_phi[idx] - e;
    g_phi[idx] = p;

    float sn, cs;
    sincosf(p, &sn, &cs);
    g_srsi[b*2*LS + l]      = cs;
    g_srsi[b*2*LS + LS + l] = sn;
    out[((size_t)b*(NSTEP+1) + (n+1))*LS + l] = cs;

    #pragma unroll
    for (int i = 0; i < 8; i++) g_dyn[idx + i*16384] = 0.f;
}

// ---------------------------------------------------------------------------
extern "C" void kernel_launch(void* const* d_in, const int* in_sizes, int n_in,
                              void* d_out, int out_size)
{
    const float *phi=0,*wr=0,*wi=0,*y=0,*W1=0,*b1=0,*W2=0,*b2=0,
                *V1=0,*c1=0,*V2=0,*c2=0;
    bool insertion = (n_in > 0 && in_sizes[0] == 16384);
    int seen262144 = 0, seen1024 = 0;
    for (int i = 0; i < n_in; i++) {
        const float* p = (const float*)d_in[i];
        switch (in_sizes[i]) {
            case 16384:    phi = p; break;
            case 4096:     y   = p; break;
            case 13107200: W1  = p; break;
            case 10240:    b1  = p; break;
            case 2621440:  W2  = p; break;
            case 2560:     b2  = p; break;
            case 1310720:  V1  = p; break;
            case 1:        c2  = p; break;
            case 262144:
                if (seen262144++ == 0) { if (insertion) wr = p; else wi = p; }
                else                   { if (insertion) wi = p; else wr = p; }
                break;
            case 1024:
                if (seen1024++ == 0)   { if (insertion) c1 = p; else V2 = p; }
                else                   { if (insertion) V2 = p; else c1 = p; }
                break;
            default: break;
        }
    }
    float* out = (float*)d_out;

    cudaFuncSetAttribute(k_static_mma,
                         cudaFuncAttributeMaxDynamicSharedMemorySize,
                         SMEM_TC_BYTES);

    k_prep      <<<2048, 256>>>(phi, wr, wi, out);
    k_wconv     <<<dim3(16,32,11), 256>>>(W1, V1);
    k_yp        <<<dim3(4,8,11), 256>>>(y, W1, V1, b1, c1);
    k_static_mma<<<dim3(8,8,11), 256, SMEM_TC_BYTES>>>();

    for (int n = 0; n < NSTEP; n++) {
        k_dyn   <<<dim3(16,16,2), 256>>>(W1, V1, n);
        k_hrho  <<<1024, 256>>>(V2, c2, out, n);
        k_etap  <<<dim3(4,16), 256>>>(W2, n);
        k_update<<<64, 256>>>(b2, out, n);
    }
}

// round 17
// speedup vs baseline: 1.0960x; 1.0960x over previous
#include <cuda_runtime.h>
#include <cuda_bf16.h>
#include <math.h>
#include <cstdint>

#define B_    64
#define LS    256
#define LW    256
#define MM    16
#define NSTEP 10
#define HH    1024
#define DD    1280
#define BM    (B_*MM)                      /* 1024 */
#define S_ENTRIES (B_*(NSTEP+1)*LS)        /* 180224: real-part floats */
#define RHO_OFF   S_ENTRIES

// -------- scratch ----------------------------------------------------------
__device__ float g_xs[BM*512];
__device__ float g_S[11u*BM*HH];
__device__ float g_yp[11*MM*HH];
__device__ float g_dyn[2*B_*HH];
__device__ float g_rho[BM];
__device__ float g_g[B_*HH];
__device__ float g_eta[B_*LS];
__device__ float g_phi[B_*LS];
__device__ float g_srsi[B_*2*LS];
// bf16 split operands for tensor k_static
__device__ __nv_bfloat16 g_xsh[BM*512];
__device__ __nv_bfloat16 g_xsl[BM*512];
__device__ __nv_bfloat16 g_WTh[11u*1024*512];   // [z][n][k] = W[z][512+k][n]
__device__ __nv_bfloat16 g_WTl[11u*1024*512];

// cp.async / ldmatrix helpers
#define CP_ASYNC16(dst, src) \
    asm volatile("cp.async.cg.shared.global [%0], [%1], 16;" \
                 :: "r"(dst), "l"(src) : "memory")
#define CP_COMMIT() asm volatile("cp.async.commit_group;" ::: "memory")
#define CP_WAIT(n)  asm volatile("cp.async.wait_group %0;" :: "n"(n) : "memory")
#define LDM_X4(r0,r1,r2,r3,a) \
    asm volatile("ldmatrix.sync.aligned.m8n8.x4.shared.b16 {%0,%1,%2,%3}, [%4];" \
                 : "=r"(r0), "=r"(r1), "=r"(r2), "=r"(r3) : "r"(a))

// ---------------------------------------------------------------------------
// P0: build xs (+bf16 hi/lo); phi copy + sincos + out slot 0; zero scratch
__global__ void k_prep(const float* __restrict__ phi,
                       const float* __restrict__ wr,
                       const float* __restrict__ wi,
                       float* __restrict__ out)
{
    int idx = blockIdx.x*256 + threadIdx.x;
    if (idx < BM*512) {
        int bm = idx >> 9, k = idx & 511;
        int b = bm >> 4, m = bm & 15;
        float v;
        if (k < 256) v = wr[((size_t)b*LW + k)*MM + m];
        else         v = wi[((size_t)b*LW + (k-256))*MM + m];
        g_xs[idx] = v;
        __nv_bfloat16 h = __float2bfloat16(v);
        g_xsh[idx] = h;
        g_xsl[idx] = __float2bfloat16(v - __bfloat162float(h));
    }
    if (idx < 2*B_*HH) g_dyn[idx] = 0.f;
    if (idx < 11*MM*HH) g_yp[idx] = 0.f;
    if (idx < B_*LS) {
        float p = phi[idx];
        g_phi[idx] = p;
        float sn, cs;
        sincosf(p, &sn, &cs);
        int b = idx >> 8, l = idx & 255;
        g_srsi[b*2*LS + l]      = cs;
        g_srsi[b*2*LS + LS + l] = sn;
        out[((size_t)b*(NSTEP+1) + 0)*LS + l] = cs;
    }
}

// W transpose+convert: WT[z][n][k] = W[z][512+k][n]  (bf16 hi/lo)
__global__ void k_wconv(const float* __restrict__ W1, const float* __restrict__ V1)
{
    __shared__ float t[32][33];
    int z = blockIdx.z, k0 = blockIdx.x*32, n0 = blockIdx.y*32;
    const float* src = (z < 10) ? (W1 + (size_t)z*DD*HH + (size_t)512*HH)
                                : (V1 + (size_t)512*HH);
    int tx = threadIdx.x & 31, ty = threadIdx.x >> 5;
    #pragma unroll
    for (int i = 0; i < 4; i++) {
        int ky = ty + i*8;
        t[ky][tx] = src[(size_t)(k0+ky)*HH + n0 + tx];
    }
    __syncthreads();
    #pragma unroll
    for (int i = 0; i < 4; i++) {
        int ny = ty + i*8;
        float v = t[tx][ny];
        __nv_bfloat16 h = __float2bfloat16(v);
        size_t o = ((size_t)z*1024 + n0 + ny)*512 + k0 + tx;
        g_WTh[o] = h;
        g_WTl[o] = __float2bfloat16(v - __bfloat162float(h));
    }
}

// P2 (split-l): yp[z][m][h] += partial; grid (4, 8, 11).
__global__ __launch_bounds__(256) void k_yp(
    const float* __restrict__ y,  const float* __restrict__ W1,
    const float* __restrict__ V1, const float* __restrict__ b1,
    const float* __restrict__ c1)
{
    int h  = blockIdx.x*256 + threadIdx.x;
    int ls = blockIdx.y;
    int z  = blockIdx.z;
    const float* Wy = (z < 10) ? (W1 + (size_t)z*DD*HH + (size_t)1024*HH)
                               : (V1 + (size_t)1024*HH);

    __shared__ float ys[32][16];
    for (int t = threadIdx.x; t < 32*16; t += 256)
        ys[t >> 4][t & 15] = y[(ls*32 + (t >> 4))*MM + (t & 15)];
    __syncthreads();

    float acc[16];
    #pragma unroll
    for (int m = 0; m < 16; m++) acc[m] = 0.f;
    #pragma unroll 4
    for (int l = 0; l < 32; l++) {
        float wv = Wy[(size_t)(ls*32 + l)*HH + h];
        #pragma unroll
        for (int m = 0; m < 16; m++) acc[m] += ys[l][m] * wv;
    }
    if (ls == 0) {
        float bias = (z < 10) ? b1[z*HH + h] : c1[h];
        #pragma unroll
        for (int m = 0; m < 16; m++) acc[m] += bias;
    }
    #pragma unroll
    for (int m = 0; m < 16; m++)
        atomicAdd(&g_yp[((size_t)z*MM + m)*HH + h], acc[m]);
}

// P1: 128x128 tile, K32 staged chunks (2-stage cp.async), ldmatrix fragments.
#define SPAD 40                            /* halfword stride, 80B rows */
#define CHW  (128*SPAD)                    /* hw per operand stage (5120) */
#define SMEM_TC_BYTES (8*CHW*2)            /* 4 ops x 2 stages = 81920B */
__global__ __launch_bounds__(256) void k_static_mma()
{
    extern __shared__ __nv_bfloat16 smtc[];

    int tid = threadIdx.x;
    int wid = tid >> 5, lane = tid & 31;
    int wr = wid >> 2, wc = wid & 3;
    int col0 = blockIdx.x*128, row0 = blockIdx.y*128, z = blockIdx.z;

    const __nv_bfloat16* Gm[4];
    Gm[0] = g_xsh + (size_t)row0*512;
    Gm[1] = g_xsl + (size_t)row0*512;
    Gm[2] = g_WTh + ((size_t)z*1024 + col0)*512;
    Gm[3] = g_WTl + ((size_t)z*1024 + col0)*512;

    float acc[4][4][4];
    #pragma unroll
    for (int mt = 0; mt < 4; mt++)
        #pragma unroll
        for (int nt = 0; nt < 4; nt++)
            #pragma unroll
            for (int r = 0; r < 4; r++) acc[mt][nt][r] = 0.f;

    uint32_t smbase = (uint32_t)__cvta_generic_to_shared(smtc);
    int u0 = tid, u1 = tid + 256;
    int r0s = u0 >> 2, g0 = u0 & 3, r1s = u1 >> 2, g1 = u1 & 3;

    int a_row = wr*64 + (lane & 15);
    int a_k   = (lane >> 4) * 8;
    int b_row = wc*32 + ((lane >> 4) << 3) + (lane & 7);
    int b_k   = ((lane >> 3) & 1) * 8;

    // prologue: stage chunk 0 into stage 0
    {
        uint32_t so = smbase;
        #pragma unroll
        for (int op = 0; op < 4; op++) {
            CP_ASYNC16(so + (uint32_t)(op*2*CHW + r0s*SPAD + g0*8)*2,
                       Gm[op] + (size_t)r0s*512 + g0*8);
            CP_ASYNC16(so + (uint32_t)(op*2*CHW + r1s*SPAD + g1*8)*2,
                       Gm[op] + (size_t)r1s*512 + g1*8);
        }
        CP_COMMIT();
    }
    CP_WAIT(0);
    __syncthreads();

    for (int kc = 0; kc < 16; kc++) {
        if (kc + 1 < 16) {
            int s = (kc + 1) & 1;
            #pragma unroll
            for (int op = 0; op < 4; op++) {
                CP_ASYNC16(smbase + (uint32_t)((op*2+s)*CHW + r0s*SPAD + g0*8)*2,
                           Gm[op] + (size_t)r0s*512 + (kc+1)*32 + g0*8);
                CP_ASYNC16(smbase + (uint32_t)((op*2+s)*CHW + r1s*SPAD + g1*8)*2,
                           Gm[op] + (size_t)r1s*512 + (kc+1)*32 + g1*8);
            }
            CP_COMMIT();
        }

        int cur = kc & 1;
        uint32_t sAh = smbase + (uint32_t)((0*2+cur)*CHW)*2;
        uint32_t sAl = smbase + (uint32_t)((1*2+cur)*CHW)*2;
        uint32_t sBh = smbase + (uint32_t)((2*2+cur)*CHW)*2;
        uint32_t sBl = smbase + (uint32_t)((3*2+cur)*CHW)*2;

        #pragma unroll
        for (int kh = 0; kh < 2; kh++) {
            uint32_t bh[4][2], bl[4][2];
            #pragma unroll
            for (int p = 0; p < 2; p++) {
                uint32_t off = (uint32_t)((b_row + p*16)*SPAD + kh*16 + b_k)*2;
                LDM_X4(bh[2*p][0], bh[2*p][1], bh[2*p+1][0], bh[2*p+1][1],
                       sBh + off);
                LDM_X4(bl[2*p][0], bl[2*p][1], bl[2*p+1][0], bl[2*p+1][1],
                       sBl + off);
            }
            #pragma unroll
            for (int mt = 0; mt < 4; mt++) {
                uint32_t off = (uint32_t)((a_row + mt*16)*SPAD + kh*16 + a_k)*2;
                uint32_t ah[4], al[4];
                LDM_X4(ah[0], ah[1], ah[2], ah[3], sAh + off);
                LDM_X4(al[0], al[1], al[2], al[3], sAl + off);
                #pragma unroll
                for (int nt = 0; nt < 4; nt++) {
                    float* c = acc[mt][nt];
                    asm volatile(
                      "mma.sync.aligned.m16n8k16.row.col.f32.bf16.bf16.f32 "
                      "{%0,%1,%2,%3}, {%4,%5,%6,%7}, {%8,%9}, {%0,%1,%2,%3};"
                      : "+f"(c[0]), "+f"(c[1]), "+f"(c[2]), "+f"(c[3])
                      : "r"(ah[0]), "r"(ah[1]), "r"(ah[2]), "r"(ah[3]),
                        "r"(bh[nt][0]), "r"(bh[nt][1]));
                    asm volatile(
                      "mma.sync.aligned.m16n8k16.row.col.f32.bf16.bf16.f32 "
                      "{%0,%1,%2,%3}, {%4,%5,%6,%7}, {%8,%9}, {%0,%1,%2,%3};"
                      : "+f"(c[0]), "+f"(c[1]), "+f"(c[2]), "+f"(c[3])
                      : "r"(ah[0]), "r"(ah[1]), "r"(ah[2]), "r"(ah[3]),
                        "r"(bl[nt][0]), "r"(bl[nt][1]));
                    asm volatile(
                      "mma.sync.aligned.m16n8k16.row.col.f32.bf16.bf16.f32 "
                      "{%0,%1,%2,%3}, {%4,%5,%6,%7}, {%8,%9}, {%0,%1,%2,%3};"
                      : "+f"(c[0]), "+f"(c[1]), "+f"(c[2]), "+f"(c[3])
                      : "r"(al[0]), "r"(al[1]), "r"(al[2]), "r"(al[3]),
                        "r"(bh[nt][0]), "r"(bh[nt][1]));
                }
            }
        }

        if (kc + 1 < 16) { CP_WAIT(0); }
        __syncthreads();
    }

    float* C = g_S + (size_t)z*BM*HH;
    #pragma unroll
    for (int mt = 0; mt < 4; mt++) {
        int mrow = row0 + wr*64 + mt*16 + (lane >> 2);
        #pragma unroll
        for (int nt = 0; nt < 4; nt++) {
            int col = col0 + wc*32 + nt*8 + (lane & 3)*2;
            float* c = acc[mt][nt];
            *(float2*)(&C[(size_t)mrow*HH + col])     = make_float2(c[0], c[1]);
            *(float2*)(&C[(size_t)(mrow+8)*HH + col]) = make_float2(c[2], c[3]);
        }
    }
}

// K2: split-K dyn GEMM. grid (16 col-tiles, 16 K-slices of 32, 2 z) = 512.
__global__ __launch_bounds__(256) void k_dyn(const float* __restrict__ W1,
                                             const float* __restrict__ V1, int n)
{
    if (blockIdx.z == 0 && blockIdx.y == 0) {
        int t = blockIdx.x*256 + threadIdx.x;
        #pragma unroll
        for (int i = 0; i < 16; i++) g_g[t + i*4096] = 0.f;
        #pragma unroll
        for (int i = 0; i < 4; i++) g_eta[t + i*4096] = 0.f;
    }

    int z = blockIdx.z;
    const float* Bmat = (z == 0) ? (W1 + (size_t)n*DD*HH) : V1;
    float* C = g_dyn + (size_t)z*B_*HH;
    const float* A = g_srsi;
    int col0 = blockIdx.x*64;
    int kbeg = blockIdx.y*32, kend = kbeg + 32;

    __shared__ float As[8][64];
    __shared__ float Bs[8][64];
    int tid = threadIdx.x;
    int tx = tid & 15, ty = tid >> 4;
    float acc[4][4];
    #pragma unroll
    for (int i = 0; i < 4; i++)
        #pragma unroll
        for (int j = 0; j < 4; j++) acc[i][j] = 0.f;

    int arow = tid >> 2, acol = (tid & 3) << 1;
    int brow = tid >> 5, bcol = (tid & 31) << 1;

    for (int k0 = kbeg; k0 < kend; k0 += 8) {
        float2 av = *(const float2*)(A + (size_t)arow*512 + k0 + acol);
        As[acol][arow] = av.x; As[acol+1][arow] = av.y;
        float2 bv = *(const float2*)(Bmat + (size_t)(k0+brow)*HH + col0 + bcol);
        Bs[brow][bcol] = bv.x; Bs[brow][bcol+1] = bv.y;
        __syncthreads();
        #pragma unroll
        for (int k = 0; k < 8; k++) {
            float a[4], bb[4];
            #pragma unroll
            for (int i = 0; i < 4; i++) a[i]  = As[k][ty*4+i];
            #pragma unroll
            for (int j = 0; j < 4; j++) bb[j] = Bs[k][tx*4+j];
            #pragma unroll
            for (int i = 0; i < 4; i++)
                #pragma unroll
                for (int j = 0; j < 4; j++) acc[i][j] += a[i]*bb[j];
        }
        __syncthreads();
    }
    #pragma unroll
    for (int i = 0; i < 4; i++)
        #pragma unroll
        for (int j = 0; j < 4; j++)
            atomicAdd(&C[(size_t)(ty*4+i)*HH + col0 + tx*4 + j], acc[i][j]);
}

// K3: h/rho; accumulates rho*h into g_g; writes rho to out.
__global__ void k_hrho(const float* __restrict__ V2, const float* __restrict__ c2,
                       float* __restrict__ out, int n)
{
    int bm = blockIdx.x, b = bm >> 4, m = bm & 15;
    const float* S1 = g_S + (size_t)n*BM*HH  + (size_t)bm*HH;
    const float* SV = g_S + (size_t)10*BM*HH + (size_t)bm*HH;
    const float* y1 = g_yp + ((size_t)n*MM  + m)*HH;
    const float* yV = g_yp + ((size_t)10*MM + m)*HH;
    const float* d1 = g_dyn + (size_t)b*HH;
    const float* dV = g_dyn + (size_t)B_*HH + (size_t)b*HH;

    float hv[4];
    float acc = 0.f;
    #pragma unroll
    for (int jj = 0; jj < 4; jj++) {
        int j = threadIdx.x + jj*256;
        hv[jj] = fmaxf(d1[j] + S1[j] + y1[j], 0.f);
        float hrv = fmaxf(dV[j] + SV[j] + yV[j], 0.f);
        acc += hrv * V2[j];
    }
    #pragma unroll
    for (int off = 16; off; off >>= 1)
        acc += __shfl_down_sync(0xffffffffu, acc, off);
    __shared__ float red[8];
    __shared__ float s_r;
    if ((threadIdx.x & 31) == 0) red[threadIdx.x >> 5] = acc;
    __syncthreads();
    if (threadIdx.x == 0) {
        float t = 0.f;
        #pragma unroll
        for (int i = 0; i < 8; i++) t += red[i];
        float r = 1.f/(1.f + __expf(-(t + c2[0])));
        s_r = r;
        g_rho[bm] = r;
        out[RHO_OFF + ((size_t)b*NSTEP + n)*MM + m] = r;
    }
    __syncthreads();
    float r = s_r;
    #pragma unroll
    for (int jj = 0; jj < 4; jj++)
        atomicAdd(&g_g[(size_t)b*HH + threadIdx.x + jj*256], r * hv[jj]);
}

// K4: split-K eta GEMM, atomicAdd into g_eta.
__global__ __launch_bounds__(256) void k_etap(const float* __restrict__ W2, int n)
{
    const float* A = g_g;
    const float* Bmat = W2 + (size_t)n*HH*LS;
    int col0 = blockIdx.x*64;
    int kbeg = blockIdx.y*64, kend = kbeg + 64;

    __shared__ float As[8][64];
    __shared__ float Bs[8][64];
    int tid = threadIdx.x;
    int tx = tid & 15, ty = tid >> 4;
    float acc[4][4];
    #pragma unroll
    for (int i = 0; i < 4; i++)
        #pragma unroll
        for (int j = 0; j < 4; j++) acc[i][j] = 0.f;

    int arow = tid >> 2, acol = (tid & 3) << 1;
    int brow = tid >> 5, bcol = (tid & 31) << 1;

    for (int k0 = kbeg; k0 < kend; k0 += 8) {
        float2 av = *(const float2*)(A + (size_t)arow*HH + k0 + acol);
        As[acol][arow] = av.x; As[acol+1][arow] = av.y;
        float2 bv = *(const float2*)(Bmat + (size_t)(k0+brow)*LS + col0 + bcol);
        Bs[brow][bcol] = bv.x; Bs[brow][bcol+1] = bv.y;
        __syncthreads();
        #pragma unroll
        for (int k = 0; k < 8; k++) {
            float a[4], bb[4];
            #pragma unroll
            for (int i = 0; i < 4; i++) a[i]  = As[k][ty*4+i];
            #pragma unroll
            for (int j = 0; j < 4; j++) bb[j] = Bs[k][tx*4+j];
            #pragma unroll
            for (int i = 0; i < 4; i++)
                #pragma unroll
                for (int j = 0; j < 4; j++) acc[i][j] += a[i]*bb[j];
        }
        __syncthreads();
    }
    #pragma unroll
    for (int i = 0; i < 4; i++)
        #pragma unroll
        for (int j = 0; j < 4; j++)
            atomicAdd(&g_eta[(size_t)(ty*4+i)*LS + col0 + tx*4 + j], acc[i][j]);
}

// K5: phi update + cis + out; zero g_dyn for next step.
__global__ void k_update(const float* __restrict__ b2, float* __restrict__ out,
                         int n)
{
    int idx = blockIdx.x*256 + threadIdx.x;
    int b = idx >> 8, l = idx & 255;
    float e = g_eta[idx];
    float rs = 0.f;
    #pragma unroll
    for (int m = 0; m < 16; m++) rs += g_rho[b*16+m];
    e += rs * b2[(size_t)n*LS + l];
    float p = g_phi[idx] - e;
    g_phi[idx] = p;

    float sn, cs;
    sincosf(p, &sn, &cs);
    g_srsi[b*2*LS + l]      = cs;
    g_srsi[b*2*LS + LS + l] = sn;
    out[((size_t)b*(NSTEP+1) + (n+1))*LS + l] = cs;

    #pragma unroll
    for (int i = 0; i < 8; i++) g_dyn[idx + i*16384] = 0.f;
}

// ---------------------------------------------------------------------------
extern "C" void kernel_launch(void* const* d_in, const int* in_sizes, int n_in,
                              void* d_out, int out_size)
{
    const float *phi=0,*wr=0,*wi=0,*y=0,*W1=0,*b1=0,*W2=0,*b2=0,
                *V1=0,*c1=0,*V2=0,*c2=0;
    bool insertion = (n_in > 0 && in_sizes[0] == 16384);
    int seen262144 = 0, seen1024 = 0;
    for (int i = 0; i < n_in; i++) {
        const float* p = (const float*)d_in[i];
        switch (in_sizes[i]) {
            case 16384:    phi = p; break;
            case 4096:     y   = p; break;
            case 13107200: W1  = p; break;
            case 10240:    b1  = p; break;
            case 2621440:  W2  = p; break;
            case 2560:     b2  = p; break;
            case 1310720:  V1  = p; break;
            case 1:        c2  = p; break;
            case 262144:
                if (seen262144++ == 0) { if (insertion) wr = p; else wi = p; }
                else                   { if (insertion) wi = p; else wr = p; }
                break;
            case 1024:
                if (seen1024++ == 0)   { if (insertion) c1 = p; else V2 = p; }
                else                   { if (insertion) V2 = p; else c1 = p; }
                break;
            default: break;
        }
    }
    float* out = (float*)d_out;

    cudaFuncSetAttribute(k_static_mma,
                         cudaFuncAttributeMaxDynamicSharedMemorySize,
                         SMEM_TC_BYTES);

    k_prep      <<<2048, 256>>>(phi, wr, wi, out);
    k_wconv     <<<dim3(16,32,11), 256>>>(W1, V1);
    k_yp        <<<dim3(4,8,11), 256>>>(y, W1, V1, b1, c1);
    k_static_mma<<<dim3(8,8,11), 256, SMEM_TC_BYTES>>>();

    for (int n = 0; n < NSTEP; n++) {
        k_dyn   <<<dim3(16,16,2), 256>>>(W1, V1, n);
        k_hrho  <<<1024, 256>>>(V2, c2, out, n);
        k_etap  <<<dim3(4,16), 256>>>(W2, n);
        k_update<<<64, 256>>>(b2, out, n);
    }
}